// round 1
// baseline (speedup 1.0000x reference)
#include <cuda_runtime.h>

// VectorQuantizer forward.
// Inputs:  d_in[0] = x      [32, 64, 32, 32] fp32  (2,097,152)
//          d_in[1] = emb_w  [1024, 64]       fp32  (65,536)
// Output (concatenated fp32, 35,651,586 elems):
//          [0 .. 2097151]           out (quantized, straight-through) [32,64,32,32]
//          [2097152]                vq_loss
//          [2097153]                perplexity
//          [2097154 .. end]         encoded one-hot [32768, 1024]

#define NVEC   32768
#define KCODES 1024
#define DDIM   64
#define KC     128     // codes per shared-memory chunk
#define TPB    256

__device__ float g_en[KCODES];     // ||e_k||^2
__device__ int   g_counts[KCODES]; // code histogram
__device__ float g_mse;            // sum of (q - x)^2

// ---- packed f32x2 FMA helpers ------------------------------------------------
__device__ __forceinline__ unsigned long long pk2(float2 v) {
    unsigned long long r;
    asm("mov.b64 %0, {%1, %2};" : "=l"(r) : "f"(v.x), "f"(v.y));
    return r;
}
__device__ __forceinline__ float2 upk2(unsigned long long v) {
    float2 r;
    asm("mov.b64 {%0, %1}, %2;" : "=f"(r.x), "=f"(r.y) : "l"(v));
    return r;
}
__device__ __forceinline__ float2 ffma2(float2 a, float2 b, float2 c) {
    unsigned long long r, A = pk2(a), B = pk2(b), C = pk2(c);
    asm("fma.rn.f32x2 %0, %1, %2, %3;" : "=l"(r) : "l"(A), "l"(B), "l"(C));
    return upk2(r);
}
__device__ __forceinline__ float2 f4lo(float4 v) { return make_float2(v.x, v.y); }
__device__ __forceinline__ float2 f4hi(float4 v) { return make_float2(v.z, v.w); }

// ---- kernel 0: init ----------------------------------------------------------
__global__ void vq_init(const float* __restrict__ emb) {
    int k = threadIdx.x;  // 1024 threads, 1 block
    if (k < KCODES) {
        float s = 0.f;
        const float* e = emb + k * DDIM;
#pragma unroll
        for (int d = 0; d < DDIM; d++) {
            float v = e[d];
            s = fmaf(v, v, s);
        }
        g_en[k] = s;
        g_counts[k] = 0;
    }
    if (k == 0) g_mse = 0.f;
}

// ---- kernel 1: distances + argmin + quantize + encoded -----------------------
__global__ __launch_bounds__(TPB) void vq_main(
    const float* __restrict__ x,
    const float* __restrict__ emb,
    float*       __restrict__ out,
    float*       __restrict__ enc)  // 8-byte aligned base, NOT 16
{
    __shared__ float es[KC][DDIM];   // 32 KB code chunk
    __shared__ float sen[KC];
    __shared__ int   sidx[TPB];
    __shared__ float sred[8];

    const int b    = blockIdx.x >> 2;        // batch index 0..31
    const int part = blockIdx.x & 3;         // quarter of the 1024 hw positions
    const int hw   = part * TPB + threadIdx.x;
    const float* xb = x + (size_t)b * 65536 + hw;

    // Load this thread's 64-dim vector (coalesced across hw) and row norm.
    float2 xv[32];
    float rn = 0.f;
#pragma unroll
    for (int d = 0; d < DDIM; d += 2) {
        float a  = xb[(size_t)d * 1024];
        float bb = xb[(size_t)(d + 1) * 1024];
        xv[d >> 1] = make_float2(a, bb);
        rn = fmaf(a, a, rn);
        rn = fmaf(bb, bb, rn);
    }

    float bestd = 3.4e38f;
    int   bestk = 0;

    for (int c = 0; c < KCODES; c += KC) {
        __syncthreads();
        // Stage 128 codes into shared memory (float4, coalesced).
        {
            const float4* src = (const float4*)(emb + (size_t)c * DDIM);
            float4* dst = (float4*)&es[0][0];
            for (int i = threadIdx.x; i < KC * (DDIM / 4); i += TPB) dst[i] = src[i];
            for (int i = threadIdx.x; i < KC; i += TPB) sen[i] = g_en[c + i];
        }
        __syncthreads();

        for (int k = 0; k < KC; k++) {
            const float4* ek = (const float4*)&es[k][0];  // 16 float4, broadcast
            float2 a0 = make_float2(0.f, 0.f), a1 = a0, a2 = a0, a3 = a0;
#pragma unroll
            for (int j = 0; j < 4; j++) {
                float4 e0 = ek[j], e1 = ek[j + 4], e2 = ek[j + 8], e3 = ek[j + 12];
                a0 = ffma2(xv[2 * j],      f4lo(e0), a0);
                a0 = ffma2(xv[2 * j + 1],  f4hi(e0), a0);
                a1 = ffma2(xv[2 * j + 8],  f4lo(e1), a1);
                a1 = ffma2(xv[2 * j + 9],  f4hi(e1), a1);
                a2 = ffma2(xv[2 * j + 16], f4lo(e2), a2);
                a2 = ffma2(xv[2 * j + 17], f4hi(e2), a2);
                a3 = ffma2(xv[2 * j + 24], f4lo(e3), a3);
                a3 = ffma2(xv[2 * j + 25], f4hi(e3), a3);
            }
            float dot  = ((a0.x + a0.y) + (a1.x + a1.y)) + ((a2.x + a2.y) + (a3.x + a3.y));
            float dist = fmaf(-2.f, dot, rn + sen[k]);
            if (dist < bestd) { bestd = dist; bestk = c + k; }  // first-index tie-break
        }
    }

    atomicAdd(&g_counts[bestk], 1);

    // Quantized output (straight-through: x + (q - x), matching ref rounding)
    // + local MSE.
    const float* eb = emb + (size_t)bestk * DDIM;
    float* ob = out + (size_t)b * 65536 + hw;
    float lm = 0.f;
#pragma unroll
    for (int d = 0; d < DDIM; d++) {
        float xd = (d & 1) ? xv[d >> 1].y : xv[d >> 1].x;
        float q  = eb[d];
        float df = q - xd;
        ob[(size_t)d * 1024] = xd + df;
        lm = fmaf(df, df, lm);
    }
#pragma unroll
    for (int o = 16; o; o >>= 1) lm += __shfl_xor_sync(0xFFFFFFFFu, lm, o);
    if ((threadIdx.x & 31) == 0) sred[threadIdx.x >> 5] = lm;
    sidx[threadIdx.x] = bestk;
    __syncthreads();
    if (threadIdx.x == 0) {
        float s = 0.f;
#pragma unroll
        for (int i = 0; i < 8; i++) s += sred[i];
        atomicAdd(&g_mse, s);
    }

    // Encoded one-hot: this block owns 256 consecutive rows of 1024 floats.
    // float2 stores (base only 8B aligned). Fully coalesced.
    {
        float2* e2 = (float2*)enc;
        const size_t base = ((size_t)b * 1024 + (size_t)part * TPB) * 512;
        for (int i = threadIdx.x; i < TPB * 512; i += TPB) {
            int r = i >> 9;
            int s = i & 511;
            int id = sidx[r];
            float2 v = make_float2(0.f, 0.f);
            if ((id >> 1) == s) { if (id & 1) v.y = 1.f; else v.x = 1.f; }
            e2[base + (size_t)i] = v;
        }
    }
}

// ---- kernel 2: losses + perplexity ------------------------------------------
__global__ void vq_fin(float* __restrict__ d_out) {
    __shared__ float sred[32];
    int k = threadIdx.x;  // 1024 threads, 1 block
    float p = (float)g_counts[k] / 32768.f;
    float t = p * logf(p + 1e-10f);
    float s = t;
#pragma unroll
    for (int o = 16; o; o >>= 1) s += __shfl_xor_sync(0xFFFFFFFFu, s, o);
    if ((k & 31) == 0) sred[k >> 5] = s;
    __syncthreads();
    if (k < 32) {
        float v = sred[k];
#pragma unroll
        for (int o = 16; o; o >>= 1) v += __shfl_xor_sync(0xFFFFFFFFu, v, o);
        if (k == 0) {
            float m = g_mse / 2097152.f;
            d_out[2097152] = m + 0.25f * m;   // commitment + BETA*emb (same forward value)
            d_out[2097153] = expf(-v);        // perplexity
        }
    }
}

extern "C" void kernel_launch(void* const* d_in, const int* in_sizes, int n_in,
                              void* d_out, int out_size) {
    const float* x   = (const float*)d_in[0];
    const float* emb = (const float*)d_in[1];
    float* out = (float*)d_out;
    float* enc = out + 2097154;

    vq_init<<<1, 1024>>>(emb);
    vq_main<<<128, TPB>>>(x, emb, out, enc);
    vq_fin<<<1, 1024>>>(out);
}